// round 17
// baseline (speedup 1.0000x reference)
#include <cuda_runtime.h>

// Problem constants (match reference)
#define B   16
#define LX  2048
#define LR  1024
#define D   768
#define T   (LX + LR + 3)   // 3075
#define D4  (D / 4)         // 192 float4 per row
#define RPB 4               // rows per CTA (B*T = 49200 divisible by 4)
#define TPB 256             // 8 warps -> 32 warps/SM at 4 CTAs
#define CPB (RPB * D4)      // 768 chunks per CTA
#define KPT (CPB / TPB)     // 3 chunks per thread

// Session champion (R12 structure) + hoisted lx/lr scalar loads.
// wall ~39.4us = mixed-stream HBM floor (226MB compulsory traffic/replay at
// ~5.7TB/s effective) + fixed replay overhead. Policy: streaming both sides
// (__ldcs/__stcs). 192 % 32 == 0 -> each warp's 32 consecutive chunks sit in
// one row: warp-uniform branch, fully coalesced 128B accesses, MLP=3.
//
// out[b,t,:] =
//   t == 0                          : CLS
//   1 <= t <= lx[b]                 : X[b, t-1]
//   t == lx[b]+1                    : RING
//   lx[b]+2 <= t < lx[b]+2+lr[b]    : Xr[b, t-lx[b]-2]
//   t == lx[b]+lr[b]+2              : END
//   else                            : 0
__global__ __launch_bounds__(TPB) void assemble_kernel(
    const float4* __restrict__ X,
    const float4* __restrict__ Xr,
    const float4* __restrict__ CLS,
    const float4* __restrict__ RING,
    const float4* __restrict__ END,
    const int*    __restrict__ lx,
    const int*    __restrict__ lr,
    float4*       __restrict__ out)
{
    const int  tid   = threadIdx.x;
    const int  row0  = blockIdx.x * RPB;
    const long base  = (long)blockIdx.x * CPB;   // first chunk of this CTA

    // Hoist lx/lr when the CTA's 4 rows share one batch (all but 15/12300 CTAs).
    const int b_first = row0 / T;
    const int b_last  = (row0 + RPB - 1) / T;
    const bool uni    = (b_first == b_last);
    const int lx_u    = __ldg(&lx[b_first]);
    const int lr_u    = __ldg(&lr[b_first]);

    float4 v[KPT];

    #pragma unroll
    for (int k = 0; k < KPT; k++) {
        const int chunk = tid + k * TPB;          // 0..767
        const int rl    = chunk / D4;             // row within CTA (0..3)
        const int c     = chunk - rl * D4;        // 0..191
        const int row   = row0 + rl;
        const int b     = uni ? b_first : (row / T);
        const int t     = row - b * T;

        const int lxb = uni ? lx_u : __ldg(&lx[b]);
        const int lrb = uni ? lr_u : __ldg(&lr[b]);

        if (t == 0) {
            v[k] = CLS[c];
        } else if (t <= lxb) {
            v[k] = __ldcs(&X[((long)b * LX + (t - 1)) * D4 + c]);
        } else if (t == lxb + 1) {
            v[k] = RING[c];
        } else if (t < lxb + 2 + lrb) {
            v[k] = __ldcs(&Xr[((long)b * LR + (t - lxb - 2)) * D4 + c]);
        } else if (t == lxb + lrb + 2) {
            v[k] = END[c];
        } else {
            v[k] = make_float4(0.f, 0.f, 0.f, 0.f);
        }
    }

    #pragma unroll
    for (int k = 0; k < KPT; k++) {
        __stcs(&out[base + tid + k * TPB], v[k]);
    }
}

extern "C" void kernel_launch(void* const* d_in, const int* in_sizes, int n_in,
                              void* d_out, int out_size)
{
    const float4* X    = (const float4*)d_in[0];
    const float4* Xr   = (const float4*)d_in[1];
    const float4* CLS  = (const float4*)d_in[2];
    const float4* RING = (const float4*)d_in[3];
    const float4* END  = (const float4*)d_in[4];
    const int*    lx   = (const int*)d_in[5];
    const int*    lr   = (const int*)d_in[6];
    float4*       out  = (float4*)d_out;

    dim3 grid((B * T) / RPB);   // 12300 CTAs
    dim3 block(TPB);            // 256 threads
    assemble_kernel<<<grid, block>>>(X, Xr, CLS, RING, END, lx, lr, out);
}